// round 1
// baseline (speedup 1.0000x reference)
#include <cuda_runtime.h>
#include <math.h>

#define BB 4
#define LL 1024
#define DD 1024
#define HH 16
#define DH 64
#define NLAYER 4
#define DFF_ 4096
#define NTOK (BB*LL)          // 4096 tokens
#define EPSV 1e-5f
#define SCALEV 0.125f         // 1/sqrt(64)

// ---------------- scratch (static device globals; no allocation) ----------------
__device__ float g_h[NTOK*DD];                       // hidden state (residual stream)
__device__ float g_y[NTOK*DD];                       // rmsnorm output
__device__ float g_qkv[NTOK*3*DD];                   // qkv projection
__device__ float g_scores[(size_t)BB*HH*LL*LL];      // attention scores / probs (268MB)
__device__ float g_attno[NTOK*DD];                   // attention output (pre-Wo)
__device__ float g_gate[NTOK*DFF_];
__device__ float g_up[NTOK*DFF_];

// ---------------- rmsnorm over D=1024, one block per row ----------------
__global__ void rmsnorm_kernel(const float* __restrict__ in, const float* __restrict__ w,
                               float* __restrict__ out) {
    int row = blockIdx.x;
    int t = threadIdx.x;  // 256
    const float4* inr = (const float4*)(in + (size_t)row * DD);
    float4 v = inr[t];
    float ss = v.x*v.x + v.y*v.y + v.z*v.z + v.w*v.w;
    __shared__ float red[256];
    red[t] = ss;
    __syncthreads();
    for (int s = 128; s > 0; s >>= 1) {
        if (t < s) red[t] += red[t + s];
        __syncthreads();
    }
    float rinv = rsqrtf(red[0] * (1.0f / DD) + EPSV);
    float4 wv = ((const float4*)w)[t];
    float4 o;
    o.x = v.x * rinv * wv.x;
    o.y = v.y * rinv * wv.y;
    o.z = v.z * rinv * wv.z;
    o.w = v.w * rinv * wv.w;
    ((float4*)(out + (size_t)row * DD))[t] = o;
}

// ---------------- generic SGEMM: C[M,N] = A[M,K] @ B[K,N] (+Res) ----------------
// 128x128 tile, BK=8, 256 threads, 8x8 micro-tile per thread.
template<bool ADD_RES>
__global__ void sgemm_kernel(const float* __restrict__ A, const float* __restrict__ Bm,
                             const float* __restrict__ Res, float* __restrict__ C,
                             int K, int N) {
    __shared__ float As[8][128];
    __shared__ float Bs[8][128];
    int tid = threadIdx.x;
    int tx = tid & 15, ty = tid >> 4;
    long Arow0 = (long)blockIdx.y * 128;
    long Bcol0 = (long)blockIdx.x * 128;
    const float* Ab = A + Arow0 * K;
    const float* Bb = Bm + Bcol0;

    float acc[8][8];
#pragma unroll
    for (int i = 0; i < 8; i++)
#pragma unroll
        for (int j = 0; j < 8; j++) acc[i][j] = 0.f;

    int arow = tid >> 1, acol = (tid & 1) * 4;   // A tile 128x8
    int brow = tid >> 5, bcol = (tid & 31) * 4;  // B tile 8x128

    for (int k0 = 0; k0 < K; k0 += 8) {
        float4 av = *(const float4*)(Ab + (long)arow * K + k0 + acol);
        As[acol + 0][arow] = av.x;
        As[acol + 1][arow] = av.y;
        As[acol + 2][arow] = av.z;
        As[acol + 3][arow] = av.w;
        float4 bv = *(const float4*)(Bb + (long)(k0 + brow) * N + bcol);
        *(float4*)(&Bs[brow][bcol]) = bv;
        __syncthreads();
#pragma unroll
        for (int k = 0; k < 8; k++) {
            float a[8], b[8];
            *(float4*)(a)     = *(float4*)(&As[k][ty * 8]);
            *(float4*)(a + 4) = *(float4*)(&As[k][ty * 8 + 4]);
            *(float4*)(b)     = *(float4*)(&Bs[k][tx * 8]);
            *(float4*)(b + 4) = *(float4*)(&Bs[k][tx * 8 + 4]);
#pragma unroll
            for (int i = 0; i < 8; i++)
#pragma unroll
                for (int j = 0; j < 8; j++) acc[i][j] += a[i] * b[j];
        }
        __syncthreads();
    }

#pragma unroll
    for (int i = 0; i < 8; i++) {
        long r = Arow0 + ty * 8 + i;
        float* crow = C + r * N + Bcol0 + tx * 8;
#pragma unroll
        for (int j4 = 0; j4 < 8; j4 += 4) {
            float4 o;
            o.x = acc[i][j4 + 0];
            o.y = acc[i][j4 + 1];
            o.z = acc[i][j4 + 2];
            o.w = acc[i][j4 + 3];
            if (ADD_RES) {
                float4 rv = *(const float4*)(Res + r * N + Bcol0 + tx * 8 + j4);
                o.x += rv.x; o.y += rv.y; o.z += rv.z; o.w += rv.w;
            }
            *(float4*)(crow + j4) = o;
        }
    }
}

// ---------------- per-head rmsnorm + RoPE on q,k (in place in qkv) ----------------
// grid: NTOK blocks; block: 1024 threads = 32 warps; warp -> (q/k, head)
__global__ void qk_prep_kernel(float* __restrict__ qkv, const float* __restrict__ qw,
                               const float* __restrict__ kw, const int* __restrict__ positions) {
    int bl = blockIdx.x;
    int warp = threadIdx.x >> 5;
    int lane = threadIdx.x & 31;
    int isk = warp >> 4;  // 0 = q, 1 = k
    int h = warp & 15;
    float* base = qkv + (size_t)bl * 3 * DD + isk * DD + h * DH;
    const float* w = isk ? kw : qw;
    float2 v = *(float2*)(base + 2 * lane);
    float ss = v.x * v.x + v.y * v.y;
#pragma unroll
    for (int o = 16; o > 0; o >>= 1) ss += __shfl_xor_sync(0xffffffffu, ss, o);
    float rinv = rsqrtf(ss * (1.0f / DH) + EPSV);
    float n0 = v.x * rinv * w[2 * lane];
    float n1 = v.y * rinv * w[2 * lane + 1];
    float o0 = n0, o1 = n1;
    if (lane < 16) {
        // inv_freq[j] = 10000^(-j/16) = exp(-ln(10000)/16 * j)
        float pos = (float)positions[bl];
        float th = pos * expf(-0.5756462732485115f * (float)lane);
        float c = cosf(th), s = sinf(th);
        o0 = n0 * c - n1 * s;
        o1 = n0 * s + n1 * c;
    }
    *(float2*)(base + 2 * lane) = make_float2(o0, o1);
}

// ---------------- attention scores: S[b,h,l,m] = scale * q_l . k_m + bias ----------------
// grid: (L/128, L/128, B*H); block 256; 128x128 tile, K=64 in two 32-chunks.
__global__ void attn_scores_kernel(const float* __restrict__ qkv,
                                   const int* __restrict__ var_id,
                                   const float* __restrict__ bias_l,  // (2,H) for this layer
                                   float* __restrict__ S) {
    int bh = blockIdx.z;
    int b = bh / HH, h = bh % HH;
    int q0 = blockIdx.y * 128, k0 = blockIdx.x * 128;
    const float* Qb = qkv + ((size_t)(b * LL + q0)) * 3 * DD + h * DH;
    const float* Kb = qkv + ((size_t)(b * LL + k0)) * 3 * DD + DD + h * DH;
    __shared__ float Qs[32][128];
    __shared__ float Ks[32][128];
    __shared__ int vq[128], vk[128];
    int tid = threadIdx.x;
    int tx = tid & 15, ty = tid >> 4;

    float acc[8][8];
#pragma unroll
    for (int i = 0; i < 8; i++)
#pragma unroll
        for (int j = 0; j < 8; j++) acc[i][j] = 0.f;

    for (int kc = 0; kc < DH; kc += 32) {
#pragma unroll
        for (int i = 0; i < 4; i++) {
            int idx = tid + i * 256;
            int row = idx >> 3, c4 = (idx & 7) * 4;
            float4 v = *(const float4*)(Qb + (size_t)row * 3 * DD + kc + c4);
            Qs[c4 + 0][row] = v.x; Qs[c4 + 1][row] = v.y;
            Qs[c4 + 2][row] = v.z; Qs[c4 + 3][row] = v.w;
            float4 u = *(const float4*)(Kb + (size_t)row * 3 * DD + kc + c4);
            Ks[c4 + 0][row] = u.x; Ks[c4 + 1][row] = u.y;
            Ks[c4 + 2][row] = u.z; Ks[c4 + 3][row] = u.w;
        }
        __syncthreads();
#pragma unroll
        for (int k = 0; k < 32; k++) {
            float a[8], bf[8];
            *(float4*)(a)      = *(float4*)(&Qs[k][ty * 8]);
            *(float4*)(a + 4)  = *(float4*)(&Qs[k][ty * 8 + 4]);
            *(float4*)(bf)     = *(float4*)(&Ks[k][tx * 8]);
            *(float4*)(bf + 4) = *(float4*)(&Ks[k][tx * 8 + 4]);
#pragma unroll
            for (int i = 0; i < 8; i++)
#pragma unroll
                for (int j = 0; j < 8; j++) acc[i][j] += a[i] * bf[j];
        }
        __syncthreads();
    }

    if (tid < 128) vq[tid] = var_id[b * LL + q0 + tid];
    else vk[tid - 128] = var_id[b * LL + k0 + (tid - 128)];
    __syncthreads();

    float bias_diff = bias_l[h];
    float bias_same = bias_l[HH + h];
    size_t Sbase = ((size_t)bh * LL + q0) * LL + k0;
#pragma unroll
    for (int i = 0; i < 8; i++) {
        int qq = ty * 8 + i;
        int vqi = vq[qq];
#pragma unroll
        for (int j4 = 0; j4 < 8; j4 += 4) {
            float4 o;
            float* pa = &acc[i][j4];
            int kk = tx * 8 + j4;
            o.x = pa[0] * SCALEV + ((vqi == vk[kk + 0]) ? bias_same : bias_diff);
            o.y = pa[1] * SCALEV + ((vqi == vk[kk + 1]) ? bias_same : bias_diff);
            o.z = pa[2] * SCALEV + ((vqi == vk[kk + 2]) ? bias_same : bias_diff);
            o.w = pa[3] * SCALEV + ((vqi == vk[kk + 3]) ? bias_same : bias_diff);
            *(float4*)(S + Sbase + (size_t)qq * LL + kk) = o;
        }
    }
}

// ---------------- softmax over last dim (1024), one block per row ----------------
__global__ void softmax_kernel(float* __restrict__ S) {
    size_t row = blockIdx.x;
    float* p = S + row * LL;
    int t = threadIdx.x;  // 256
    float4 v = ((float4*)p)[t];
    float m = fmaxf(fmaxf(v.x, v.y), fmaxf(v.z, v.w));
    __shared__ float red[256];
    red[t] = m;
    __syncthreads();
    for (int s = 128; s > 0; s >>= 1) {
        if (t < s) red[t] = fmaxf(red[t], red[t + s]);
        __syncthreads();
    }
    m = red[0];
    __syncthreads();
    v.x = expf(v.x - m); v.y = expf(v.y - m);
    v.z = expf(v.z - m); v.w = expf(v.w - m);
    red[t] = v.x + v.y + v.z + v.w;
    __syncthreads();
    for (int s = 128; s > 0; s >>= 1) {
        if (t < s) red[t] += red[t + s];
        __syncthreads();
    }
    float inv = 1.0f / red[0];
    v.x *= inv; v.y *= inv; v.z *= inv; v.w *= inv;
    ((float4*)p)[t] = v;
}

// ---------------- attn output: O[b,q,h,:] = sum_m P[b,h,q,m] * V[b,m,h,:] ----------------
// grid: (L/128, B*H); block 256; tile 128 q-rows x 64 cols, BK=32.
__global__ void attn_av_kernel(const float* __restrict__ S, const float* __restrict__ qkv,
                               float* __restrict__ O) {
    int bh = blockIdx.y;
    int b = bh / HH, h = bh % HH;
    int q0 = blockIdx.x * 128;
    const float* Sb = S + ((size_t)bh * LL + q0) * LL;
    const float* Vb = qkv + (size_t)b * LL * 3 * DD + 2 * DD + h * DH;
    __shared__ float Ps[32][128];
    __shared__ float Vs[32][64];
    int tid = threadIdx.x;
    int tx = tid & 7, ty = tid >> 3;  // tx: 8 col-groups of 8; ty: 32 row-groups of 4

    float acc[4][8];
#pragma unroll
    for (int i = 0; i < 4; i++)
#pragma unroll
        for (int j = 0; j < 8; j++) acc[i][j] = 0.f;

    for (int m0 = 0; m0 < LL; m0 += 32) {
#pragma unroll
        for (int i = 0; i < 4; i++) {
            int idx = tid + i * 256;
            int row = idx >> 3, c4 = (idx & 7) * 4;
            float4 v = *(const float4*)(Sb + (size_t)row * LL + m0 + c4);
            Ps[c4 + 0][row] = v.x; Ps[c4 + 1][row] = v.y;
            Ps[c4 + 2][row] = v.z; Ps[c4 + 3][row] = v.w;
        }
#pragma unroll
        for (int i = 0; i < 2; i++) {
            int id2 = tid + i * 256;
            int row = id2 >> 4, c4 = (id2 & 15) * 4;
            *(float4*)(&Vs[row][c4]) = *(const float4*)(Vb + (size_t)(m0 + row) * 3 * DD + c4);
        }
        __syncthreads();
#pragma unroll
        for (int k = 0; k < 32; k++) {
            float a[4], bv[8];
            *(float4*)(a)      = *(float4*)(&Ps[k][ty * 4]);
            *(float4*)(bv)     = *(float4*)(&Vs[k][tx * 8]);
            *(float4*)(bv + 4) = *(float4*)(&Vs[k][tx * 8 + 4]);
#pragma unroll
            for (int i = 0; i < 4; i++)
#pragma unroll
                for (int j = 0; j < 8; j++) acc[i][j] += a[i] * bv[j];
        }
        __syncthreads();
    }

#pragma unroll
    for (int i = 0; i < 4; i++) {
        float* orow = O + ((size_t)(b * LL + q0 + ty * 4 + i)) * DD + h * DH + tx * 8;
#pragma unroll
        for (int j4 = 0; j4 < 8; j4 += 4) {
            float4 o;
            o.x = acc[i][j4 + 0]; o.y = acc[i][j4 + 1];
            o.z = acc[i][j4 + 2]; o.w = acc[i][j4 + 3];
            *(float4*)(orow + j4) = o;
        }
    }
}

// ---------------- g = silu(g) * u (float4) ----------------
__global__ void silu_mul_kernel(float* __restrict__ g, const float* __restrict__ u) {
    size_t i = (size_t)blockIdx.x * blockDim.x + threadIdx.x;
    float4 gv = ((float4*)g)[i];
    float4 uv = ((const float4*)u)[i];
    gv.x = (gv.x / (1.f + expf(-gv.x))) * uv.x;
    gv.y = (gv.y / (1.f + expf(-gv.y))) * uv.y;
    gv.z = (gv.z / (1.f + expf(-gv.z))) * uv.z;
    gv.w = (gv.w / (1.f + expf(-gv.w))) * uv.w;
    ((float4*)g)[i] = gv;
}

// ---------------- host orchestration ----------------
extern "C" void kernel_launch(void* const* d_in, const int* in_sizes, int n_in,
                              void* d_out, int out_size) {
    const float* x         = (const float*)d_in[0];
    const int*   var_id    = (const int*)d_in[1];
    const int*   positions = (const int*)d_in[2];
    const float* Wqkv      = (const float*)d_in[3];
    const float* Wo        = (const float*)d_in[4];
    const float* n1w       = (const float*)d_in[5];
    const float* n2w       = (const float*)d_in[6];
    const float* qnw       = (const float*)d_in[7];
    const float* knw       = (const float*)d_in[8];
    const float* bias_emb  = (const float*)d_in[9];
    const float* Wg        = (const float*)d_in[10];
    const float* Wu        = (const float*)d_in[11];
    const float* Wd        = (const float*)d_in[12];
    const float* fnw       = (const float*)d_in[13];
    float* out = (float*)d_out;

    float *h, *y, *qkv, *scores, *attno, *gate, *up;
    cudaGetSymbolAddress((void**)&h, g_h);
    cudaGetSymbolAddress((void**)&y, g_y);
    cudaGetSymbolAddress((void**)&qkv, g_qkv);
    cudaGetSymbolAddress((void**)&scores, g_scores);
    cudaGetSymbolAddress((void**)&attno, g_attno);
    cudaGetSymbolAddress((void**)&gate, g_gate);
    cudaGetSymbolAddress((void**)&up, g_up);

    cudaMemcpyAsync(h, x, (size_t)NTOK * DD * sizeof(float), cudaMemcpyDeviceToDevice);

    for (int l = 0; l < NLAYER; l++) {
        // attention block
        rmsnorm_kernel<<<NTOK, 256>>>(h, n1w + (size_t)l * DD, y);
        sgemm_kernel<false><<<dim3(3 * DD / 128, NTOK / 128), 256>>>(
            y, Wqkv + (size_t)l * DD * 3 * DD, nullptr, qkv, DD, 3 * DD);
        qk_prep_kernel<<<NTOK, 1024>>>(qkv, qnw + (size_t)l * DH, knw + (size_t)l * DH, positions);
        attn_scores_kernel<<<dim3(LL / 128, LL / 128, BB * HH), 256>>>(
            qkv, var_id, bias_emb + (size_t)l * 2 * HH, scores);
        softmax_kernel<<<BB * HH * LL, 256>>>(scores);
        attn_av_kernel<<<dim3(LL / 128, BB * HH), 256>>>(scores, qkv, attno);
        sgemm_kernel<true><<<dim3(DD / 128, NTOK / 128), 256>>>(
            attno, Wo + (size_t)l * DD * DD, h, h, DD, DD);

        // FFN block
        rmsnorm_kernel<<<NTOK, 256>>>(h, n2w + (size_t)l * DD, y);
        sgemm_kernel<false><<<dim3(DFF_ / 128, NTOK / 128), 256>>>(
            y, Wg + (size_t)l * DD * DFF_, nullptr, gate, DD, DFF_);
        sgemm_kernel<false><<<dim3(DFF_ / 128, NTOK / 128), 256>>>(
            y, Wu + (size_t)l * DD * DFF_, nullptr, up, DD, DFF_);
        silu_mul_kernel<<<((size_t)NTOK * DFF_ / 4) / 256, 256>>>(gate, up);
        sgemm_kernel<true><<<dim3(DD / 128, NTOK / 128), 256>>>(
            gate, Wd + (size_t)l * DFF_ * DD, h, h, DFF_, DD);
    }

    rmsnorm_kernel<<<NTOK, 256>>>(h, fnw, out);
}

// round 2
// speedup vs baseline: 5.6357x; 5.6357x over previous
#include <cuda_runtime.h>
#include <cuda_fp16.h>
#include <math.h>
#include <stdint.h>

#define BB 4
#define LL 1024
#define DD 1024
#define HH 16
#define DH 64
#define NLAYER 4
#define DFF_ 4096
#define NTOK (BB*LL)
#define EPSV 1e-5f
#define SCALEV 0.125f

// ---------------- static scratch ----------------
__device__ float  g_h[NTOK*DD];
__device__ __half g_yh[NTOK*DD];
__device__ __half g_qkv[NTOK*3*DD];
__device__ __half g_qh[(size_t)BB*HH*LL*DH];
__device__ __half g_kh[(size_t)BB*HH*LL*DH];
__device__ __half g_vh[(size_t)BB*HH*LL*DH];
__device__ float  g_scores[(size_t)BB*HH*LL*LL];
__device__ __half g_probs[(size_t)BB*HH*LL*LL];
__device__ __half g_attno[NTOK*DD];
__device__ __half g_gate[(size_t)NTOK*DFF_];
__device__ __half g_up[(size_t)NTOK*DFF_];
__device__ __half g_gact[(size_t)NTOK*DFF_];
__device__ __half g_wqkv[(size_t)NLAYER*DD*3*DD];
__device__ __half g_wo[(size_t)NLAYER*DD*DD];
__device__ __half g_wg[(size_t)NLAYER*DD*DFF_];
__device__ __half g_wu[(size_t)NLAYER*DD*DFF_];
__device__ __half g_wd[(size_t)NLAYER*DFF_*DD];

// ---------------- PTX helpers ----------------
__device__ __forceinline__ uint32_t smem_u32(const void* p) {
    return (uint32_t)__cvta_generic_to_shared(p);
}
__device__ __forceinline__ void cp16(uint32_t s, const void* g) {
    asm volatile("cp.async.cg.shared.global [%0], [%1], 16;\n" :: "r"(s), "l"(g));
}
__device__ __forceinline__ void cp_commit() { asm volatile("cp.async.commit_group;\n"); }
__device__ __forceinline__ void cp_wait0()  { asm volatile("cp.async.wait_group 0;\n"); }

__device__ __forceinline__ void ldmx4(uint32_t* r, uint32_t a) {
    asm volatile("ldmatrix.sync.aligned.m8n8.x4.shared.b16 {%0,%1,%2,%3}, [%4];\n"
        : "=r"(r[0]), "=r"(r[1]), "=r"(r[2]), "=r"(r[3]) : "r"(a));
}
__device__ __forceinline__ void ldmx4t(uint32_t* r, uint32_t a) {
    asm volatile("ldmatrix.sync.aligned.m8n8.x4.trans.shared.b16 {%0,%1,%2,%3}, [%4];\n"
        : "=r"(r[0]), "=r"(r[1]), "=r"(r[2]), "=r"(r[3]) : "r"(a));
}
__device__ __forceinline__ void mma_f16(float* c, const uint32_t* a, const uint32_t* b) {
    asm volatile("mma.sync.aligned.m16n8k16.row.col.f32.f16.f16.f32 "
        "{%0,%1,%2,%3}, {%4,%5,%6,%7}, {%8,%9}, {%0,%1,%2,%3};\n"
        : "+f"(c[0]), "+f"(c[1]), "+f"(c[2]), "+f"(c[3])
        : "r"(a[0]), "r"(a[1]), "r"(a[2]), "r"(a[3]), "r"(b[0]), "r"(b[1]));
}

// ---------------- float -> half cast ----------------
__global__ void cast_f2h(const float* __restrict__ s, __half* __restrict__ d, long n) {
    long i = ((long)blockIdx.x * blockDim.x + threadIdx.x) * 4;
    if (i < n) {
        float4 v = *(const float4*)(s + i);
        __half2* o = (__half2*)(d + i);
        o[0] = __floats2half2_rn(v.x, v.y);
        o[1] = __floats2half2_rn(v.z, v.w);
    }
}

// ---------------- rmsnorm: fp32 in, fp16 or fp32 out ----------------
template<int OUTH>
__global__ void rmsnorm_kernel(const float* __restrict__ in, const float* __restrict__ w,
                               void* __restrict__ outv) {
    int row = blockIdx.x;
    int t = threadIdx.x;  // 256
    float4 v = ((const float4*)(in + (size_t)row * DD))[t];
    float ss = v.x*v.x + v.y*v.y + v.z*v.z + v.w*v.w;
    __shared__ float red[256];
    red[t] = ss;
    __syncthreads();
    for (int s = 128; s > 0; s >>= 1) {
        if (t < s) red[t] += red[t + s];
        __syncthreads();
    }
    float rinv = rsqrtf(red[0] * (1.0f / DD) + EPSV);
    float4 wv = ((const float4*)w)[t];
    float o0 = v.x * rinv * wv.x, o1 = v.y * rinv * wv.y;
    float o2 = v.z * rinv * wv.z, o3 = v.w * rinv * wv.w;
    if (OUTH) {
        __half2* o = (__half2*)((__half*)outv + (size_t)row * DD) + 2 * t;
        o[0] = __floats2half2_rn(o0, o1);
        o[1] = __floats2half2_rn(o2, o3);
    } else {
        float4 o; o.x = o0; o.y = o1; o.z = o2; o.w = o3;
        ((float4*)((float*)outv + (size_t)row * DD))[t] = o;
    }
}

// ---------------- generic mma GEMM ----------------
// BM=128, BK=32, 128 threads = 4 warps in 2x2, warp tile 64 x (BN_/2).
// A [M,K] fp16 row-major. B [K,N] fp16 row-major (n contiguous).
// OUT: 1 = fp32 out + fp32 residual, 2 = fp16 out.
// CLAY: 0 = C + z*sC, 1 = attention-out layout C + (z/H)*L*ldc + (z%H)*DH.
template<int BN_, int OUT, int CLAY>
__global__ void __launch_bounds__(128)
gemm_mma(const __half* __restrict__ A, const __half* __restrict__ B,
         const float* __restrict__ Res, void* __restrict__ Cv,
         int M, int N, int K, long sA, long sB, long sC, int ldc)
{
    constexpr int BM = 128, BK = 32;
    constexpr int WN = BN_ / 2;
    constexpr int NT = WN / 8;
    constexpr int AP = BK + 8;
    constexpr int BP = BN_ + 8;
    __shared__ __half As[2][BM * AP];
    __shared__ __half Bs[2][BK * BP];

    const int z = blockIdx.z;
    const __half* Az = A + (size_t)z * sA;
    const __half* Bz = B + (size_t)z * sB;
    const int tid = threadIdx.x, warp = tid >> 5, lane = tid & 31;
    const int wm = warp >> 1, wn = warp & 1;
    const long row0 = (long)blockIdx.y * BM;
    const long col0 = (long)blockIdx.x * BN_;

    float acc[4][NT][4];
#pragma unroll
    for (int i = 0; i < 4; i++)
#pragma unroll
        for (int j = 0; j < NT; j++)
#pragma unroll
            for (int q = 0; q < 4; q++) acc[i][j][q] = 0.f;

    const int TK = K / BK;
    auto load = [&](int s, int kt) {
        const int kb = kt * BK;
#pragma unroll
        for (int i = 0; i < 4; i++) {
            int lin = tid + i * 128;
            int r = lin >> 2, c = (lin & 3) * 8;
            cp16(smem_u32(&As[s][r * AP + c]), Az + (row0 + r) * (size_t)K + kb + c);
        }
#pragma unroll
        for (int i = 0; i < BN_ / 32; i++) {
            int lin = tid + i * 128;
            int r = lin / (BN_ / 8), c = (lin % (BN_ / 8)) * 8;
            cp16(smem_u32(&Bs[s][r * BP + c]), Bz + (size_t)(kb + r) * N + col0 + c);
        }
    };

    load(0, 0); cp_commit();
    for (int t = 0; t < TK; t++) {
        cp_wait0();
        __syncthreads();
        if (t + 1 < TK) { load((t + 1) & 1, t + 1); cp_commit(); }
        const int s = t & 1;
#pragma unroll
        for (int ks = 0; ks < 2; ks++) {
            const int k0 = ks * 16;
            uint32_t a[4][4];
#pragma unroll
            for (int mt = 0; mt < 4; mt++) {
                int r = wm * 64 + mt * 16 + (lane & 15);
                int c = k0 + (lane >> 4) * 8;
                ldmx4(a[mt], smem_u32(&As[s][r * AP + c]));
            }
            uint32_t bf[NT][2];
#pragma unroll
            for (int np = 0; np < NT / 2; np++) {
                int r = k0 + (lane & 15);
                int c = wn * WN + np * 16 + (lane >> 4) * 8;
                uint32_t rr[4];
                ldmx4t(rr, smem_u32(&Bs[s][r * BP + c]));
                bf[np*2][0] = rr[0]; bf[np*2][1] = rr[1];
                bf[np*2+1][0] = rr[2]; bf[np*2+1][1] = rr[3];
            }
#pragma unroll
            for (int mt = 0; mt < 4; mt++)
#pragma unroll
                for (int nt = 0; nt < NT; nt++)
                    mma_f16(acc[mt][nt], a[mt], bf[nt]);
        }
        __syncthreads();
    }

    size_t cb;
    if (CLAY == 0) cb = (size_t)z * sC;
    else { int bb = z / HH, hh = z % HH; cb = (size_t)bb * LL * ldc + (size_t)hh * DH; }

#pragma unroll
    for (int mt = 0; mt < 4; mt++) {
        long r = row0 + wm * 64 + mt * 16 + (lane >> 2);
#pragma unroll
        for (int nt = 0; nt < NT; nt++) {
            long c = col0 + wn * WN + nt * 8 + (lane & 3) * 2;
            float* ac = acc[mt][nt];
            if (OUT == 2) {
                __half* C = (__half*)Cv;
                *(__half2*)(C + cb + r * ldc + c)       = __floats2half2_rn(ac[0], ac[1]);
                *(__half2*)(C + cb + (r + 8) * ldc + c) = __floats2half2_rn(ac[2], ac[3]);
            } else {
                float* C = (float*)Cv;
                float2 v0 = make_float2(ac[0], ac[1]);
                float2 v1 = make_float2(ac[2], ac[3]);
                if (OUT == 1) {
                    float2 r0 = *(const float2*)(Res + cb + r * ldc + c);
                    float2 r1 = *(const float2*)(Res + cb + (r + 8) * ldc + c);
                    v0.x += r0.x; v0.y += r0.y; v1.x += r1.x; v1.y += r1.y;
                }
                *(float2*)(C + cb + r * ldc + c)       = v0;
                *(float2*)(C + cb + (r + 8) * ldc + c) = v1;
            }
        }
    }
}

// ---------------- per-head rmsnorm + RoPE + split to [b,h,l,d] fp16 ----------------
__global__ void qk_prep_kernel(const __half* __restrict__ qkv, const float* __restrict__ qw,
                               const float* __restrict__ kw, const int* __restrict__ positions,
                               __half* __restrict__ qh, __half* __restrict__ kh,
                               __half* __restrict__ vh) {
    int bl = blockIdx.x;
    int b = bl >> 10, l = bl & 1023;
    int warp = threadIdx.x >> 5;
    int lane = threadIdx.x & 31;
    int isk = warp >> 4;
    int h = warp & 15;
    const __half* base = qkv + (size_t)bl * 3 * DD + isk * DD + h * DH;
    const float* w = isk ? kw : qw;
    float2 v = __half22float2(*(const __half2*)(base + 2 * lane));
    float ss = v.x * v.x + v.y * v.y;
#pragma unroll
    for (int o = 16; o > 0; o >>= 1) ss += __shfl_xor_sync(0xffffffffu, ss, o);
    float rinv = rsqrtf(ss * (1.0f / DH) + EPSV);
    float n0 = v.x * rinv * w[2 * lane];
    float n1 = v.y * rinv * w[2 * lane + 1];
    float o0 = n0, o1 = n1;
    if (lane < 16) {
        float pos = (float)positions[bl];
        float th = pos * expf(-0.5756462732485115f * (float)lane);
        float c = cosf(th), s = sinf(th);
        o0 = n0 * c - n1 * s;
        o1 = n0 * s + n1 * c;
    }
    __half* outp = (isk ? kh : qh) + (((size_t)(b * HH + h)) * LL + l) * DH + 2 * lane;
    *(__half2*)outp = __floats2half2_rn(o0, o1);
    if (!isk) {
        __half2 vv = *(const __half2*)(qkv + (size_t)bl * 3 * DD + 2 * DD + h * DH + 2 * lane);
        *(__half2*)(vh + (((size_t)(b * HH + h)) * LL + l) * DH + 2 * lane) = vv;
    }
}

// ---------------- attention scores via mma: S = scale * Q K^T + bias ----------------
// Q,K: [BH][L][64] fp16. K=64 single shot. 128 threads, warp grid 2x2, warp 64x64.
__global__ void __launch_bounds__(128)
attn_scores_mma(const __half* __restrict__ Q, const __half* __restrict__ Kh,
                const int* __restrict__ var_id, const float* __restrict__ bias_l,
                float* __restrict__ S)
{
    constexpr int AP = DH + 8;  // 72
    __shared__ __half Qs[128 * AP];
    __shared__ __half Ks[128 * AP];
    __shared__ int vq[128], vk[128];
    int zbh = blockIdx.z;
    int b = zbh >> 4, h = zbh & 15;
    int q0 = blockIdx.y * 128, k0b = blockIdx.x * 128;
    const __half* Qz = Q + ((size_t)zbh * LL + q0) * DH;
    const __half* Kz = Kh + ((size_t)zbh * LL + k0b) * DH;
    int tid = threadIdx.x, warp = tid >> 5, lane = tid & 31;
    int wm = warp >> 1, wn = warp & 1;

#pragma unroll
    for (int i = 0; i < 8; i++) {
        int lin = tid + i * 128;
        int r = lin >> 3, c = (lin & 7) * 8;
        cp16(smem_u32(&Qs[r * AP + c]), Qz + (size_t)r * DH + c);
        cp16(smem_u32(&Ks[r * AP + c]), Kz + (size_t)r * DH + c);
    }
    cp_commit();
    vq[tid] = var_id[b * LL + q0 + tid];
    vk[tid] = var_id[b * LL + k0b + tid];
    cp_wait0();
    __syncthreads();

    float acc[4][8][4];
#pragma unroll
    for (int i = 0; i < 4; i++)
#pragma unroll
        for (int j = 0; j < 8; j++)
#pragma unroll
            for (int q = 0; q < 4; q++) acc[i][j][q] = 0.f;

#pragma unroll
    for (int ks = 0; ks < 4; ks++) {
        int k0 = ks * 16;
        uint32_t a[4][4];
#pragma unroll
        for (int mt = 0; mt < 4; mt++) {
            int r = wm * 64 + mt * 16 + (lane & 15);
            int c = k0 + (lane >> 4) * 8;
            ldmx4(a[mt], smem_u32(&Qs[r * AP + c]));
        }
        uint32_t bf[8][2];
#pragma unroll
        for (int np = 0; np < 4; np++) {
            // non-trans ldmatrix over [n][k] storage yields B fragments directly
            int r = wn * 64 + np * 16 + (lane & 7) + ((lane >> 4) & 1) * 8;
            int c = k0 + ((lane >> 3) & 1) * 8;
            uint32_t rr[4];
            ldmx4(rr, smem_u32(&Ks[r * AP + c]));
            bf[np*2][0] = rr[0]; bf[np*2][1] = rr[1];
            bf[np*2+1][0] = rr[2]; bf[np*2+1][1] = rr[3];
        }
#pragma unroll
        for (int mt = 0; mt < 4; mt++)
#pragma unroll
            for (int nt = 0; nt < 8; nt++)
                mma_f16(acc[mt][nt], a[mt], bf[nt]);
    }

    float bd = bias_l[h], bs = bias_l[HH + h];
    size_t Sb = ((size_t)zbh * LL + q0) * LL + k0b;
#pragma unroll
    for (int mt = 0; mt < 4; mt++) {
        int rl = wm * 64 + mt * 16 + (lane >> 2);
        int v0 = vq[rl], v1 = vq[rl + 8];
#pragma unroll
        for (int nt = 0; nt < 8; nt++) {
            int cl = wn * 64 + nt * 8 + (lane & 3) * 2;
            int w0 = vk[cl], w1 = vk[cl + 1];
            float* ac = acc[mt][nt];
            float2 o0 = make_float2(ac[0] * SCALEV + (v0 == w0 ? bs : bd),
                                    ac[1] * SCALEV + (v0 == w1 ? bs : bd));
            float2 o1 = make_float2(ac[2] * SCALEV + (v1 == w0 ? bs : bd),
                                    ac[3] * SCALEV + (v1 == w1 ? bs : bd));
            *(float2*)(S + Sb + (size_t)rl * LL + cl)       = o0;
            *(float2*)(S + Sb + (size_t)(rl + 8) * LL + cl) = o1;
        }
    }
}

// ---------------- softmax (fp32 in, fp16 out) ----------------
__global__ void softmax_kernel(const float* __restrict__ S, __half* __restrict__ P) {
    size_t row = blockIdx.x;
    const float* p = S + row * LL;
    int t = threadIdx.x;  // 256
    float4 v = ((const float4*)p)[t];
    float m = fmaxf(fmaxf(v.x, v.y), fmaxf(v.z, v.w));
    __shared__ float red[256];
    red[t] = m;
    __syncthreads();
    for (int s = 128; s > 0; s >>= 1) {
        if (t < s) red[t] = fmaxf(red[t], red[t + s]);
        __syncthreads();
    }
    m = red[0];
    __syncthreads();
    v.x = expf(v.x - m); v.y = expf(v.y - m);
    v.z = expf(v.z - m); v.w = expf(v.w - m);
    red[t] = v.x + v.y + v.z + v.w;
    __syncthreads();
    for (int s = 128; s > 0; s >>= 1) {
        if (t < s) red[t] += red[t + s];
        __syncthreads();
    }
    float inv = 1.0f / red[0];
    __half2* o = (__half2*)(P + row * LL) + 2 * t;
    o[0] = __floats2half2_rn(v.x * inv, v.y * inv);
    o[1] = __floats2half2_rn(v.z * inv, v.w * inv);
}

// ---------------- silu(gate) * up -> fp16 ----------------
__global__ void silu_mul_kernel(const __half* __restrict__ g, const __half* __restrict__ u,
                                __half* __restrict__ o) {
    size_t i = (size_t)blockIdx.x * blockDim.x + threadIdx.x;
    float2 gf = __half22float2(((const __half2*)g)[i]);
    float2 uf = __half22float2(((const __half2*)u)[i]);
    float r0 = (gf.x / (1.f + expf(-gf.x))) * uf.x;
    float r1 = (gf.y / (1.f + expf(-gf.y))) * uf.y;
    ((__half2*)o)[i] = __floats2half2_rn(r0, r1);
}

// ---------------- host orchestration ----------------
extern "C" void kernel_launch(void* const* d_in, const int* in_sizes, int n_in,
                              void* d_out, int out_size) {
    const float* x         = (const float*)d_in[0];
    const int*   var_id    = (const int*)d_in[1];
    const int*   positions = (const int*)d_in[2];
    const float* Wqkv      = (const float*)d_in[3];
    const float* Wo        = (const float*)d_in[4];
    const float* n1w       = (const float*)d_in[5];
    const float* n2w       = (const float*)d_in[6];
    const float* qnw       = (const float*)d_in[7];
    const float* knw       = (const float*)d_in[8];
    const float* bias_emb  = (const float*)d_in[9];
    const float* Wg        = (const float*)d_in[10];
    const float* Wu        = (const float*)d_in[11];
    const float* Wd        = (const float*)d_in[12];
    const float* fnw       = (const float*)d_in[13];
    float* out = (float*)d_out;

    float  *h, *scores;
    __half *yh, *qkv, *qh, *kh, *vh, *probs, *attno, *gate, *up, *gact;
    __half *wqkv, *wo, *wg, *wu, *wd;
    cudaGetSymbolAddress((void**)&h, g_h);
    cudaGetSymbolAddress((void**)&scores, g_scores);
    cudaGetSymbolAddress((void**)&yh, g_yh);
    cudaGetSymbolAddress((void**)&qkv, g_qkv);
    cudaGetSymbolAddress((void**)&qh, g_qh);
    cudaGetSymbolAddress((void**)&kh, g_kh);
    cudaGetSymbolAddress((void**)&vh, g_vh);
    cudaGetSymbolAddress((void**)&probs, g_probs);
    cudaGetSymbolAddress((void**)&attno, g_attno);
    cudaGetSymbolAddress((void**)&gate, g_gate);
    cudaGetSymbolAddress((void**)&up, g_up);
    cudaGetSymbolAddress((void**)&gact, g_gact);
    cudaGetSymbolAddress((void**)&wqkv, g_wqkv);
    cudaGetSymbolAddress((void**)&wo, g_wo);
    cudaGetSymbolAddress((void**)&wg, g_wg);
    cudaGetSymbolAddress((void**)&wu, g_wu);
    cudaGetSymbolAddress((void**)&wd, g_wd);

    // cast all weights to fp16
    auto cast = [](const float* s, __half* d, long n) {
        cast_f2h<<<(unsigned)((n / 4 + 255) / 256), 256>>>(s, d, n);
    };
    cast(Wqkv, wqkv, (long)NLAYER * DD * 3 * DD);
    cast(Wo,   wo,   (long)NLAYER * DD * DD);
    cast(Wg,   wg,   (long)NLAYER * DD * DFF_);
    cast(Wu,   wu,   (long)NLAYER * DD * DFF_);
    cast(Wd,   wd,   (long)NLAYER * DFF_ * DD);

    cudaMemcpyAsync(h, x, (size_t)NTOK * DD * sizeof(float), cudaMemcpyDeviceToDevice);

    for (int l = 0; l < NLAYER; l++) {
        // ---- attention ----
        rmsnorm_kernel<1><<<NTOK, 256>>>(h, n1w + (size_t)l * DD, yh);
        gemm_mma<128, 2, 0><<<dim3(3 * DD / 128, NTOK / 128, 1), 128>>>(
            yh, wqkv + (size_t)l * DD * 3 * DD, nullptr, qkv,
            NTOK, 3 * DD, DD, 0, 0, 0, 3 * DD);
        qk_prep_kernel<<<NTOK, 1024>>>(qkv, qnw + (size_t)l * DH, knw + (size_t)l * DH,
                                       positions, qh, kh, vh);
        attn_scores_mma<<<dim3(LL / 128, LL / 128, BB * HH), 128>>>(
            qh, kh, var_id, bias_emb + (size_t)l * 2 * HH, scores);
        softmax_kernel<<<BB * HH * LL, 256>>>(scores, probs);
        gemm_mma<64, 2, 1><<<dim3(1, LL / 128, BB * HH), 128>>>(
            probs, vh, nullptr, attno,
            LL, DH, LL, (long)LL * LL, (long)LL * DH, 0, DD);
        gemm_mma<128, 1, 0><<<dim3(DD / 128, NTOK / 128, 1), 128>>>(
            attno, wo + (size_t)l * DD * DD, h, h,
            NTOK, DD, DD, 0, 0, 0, DD);

        // ---- FFN ----
        rmsnorm_kernel<1><<<NTOK, 256>>>(h, n2w + (size_t)l * DD, yh);
        gemm_mma<128, 2, 0><<<dim3(DFF_ / 128, NTOK / 128, 1), 128>>>(
            yh, wg + (size_t)l * DD * DFF_, nullptr, gate,
            NTOK, DFF_, DD, 0, 0, 0, DFF_);
        gemm_mma<128, 2, 0><<<dim3(DFF_ / 128, NTOK / 128, 1), 128>>>(
            yh, wu + (size_t)l * DD * DFF_, nullptr, up,
            NTOK, DFF_, DD, 0, 0, 0, DFF_);
        silu_mul_kernel<<<(unsigned)(((size_t)NTOK * DFF_ / 2) / 256), 256>>>(gate, up, gact);
        gemm_mma<128, 1, 0><<<dim3(DD / 128, NTOK / 128, 1), 128>>>(
            gact, wd + (size_t)l * DFF_ * DD, h, h,
            NTOK, DD, DFF_, 0, 0, 0, DD);
    }

    rmsnorm_kernel<0><<<NTOK, 256>>>(h, fnw, out);
}

// round 3
// speedup vs baseline: 6.5666x; 1.1652x over previous
#include <cuda_runtime.h>
#include <cuda_fp16.h>
#include <math.h>
#include <stdint.h>

#define BB 4
#define LL 1024
#define DD 1024
#define HH 16
#define DH 64
#define NLAYER 4
#define DFF_ 4096
#define NTOK (BB*LL)
#define EPSV 1e-5f
#define QSCALE 0.18033688011112042f   // (1/sqrt(64)) * log2(e)
#define LOG2E 1.4426950408889634f

// ---------------- static scratch ----------------
__device__ float  g_h[NTOK*DD];
__device__ __half g_yh[NTOK*DD];
__device__ __half g_qkv[NTOK*3*DD];
__device__ __half g_qh[(size_t)BB*HH*LL*DH];
__device__ __half g_kh[(size_t)BB*HH*LL*DH];
__device__ __half g_vh[(size_t)BB*HH*LL*DH];
__device__ __half g_attno[NTOK*DD];
__device__ __half g_gate[(size_t)NTOK*DFF_];
__device__ __half g_up[(size_t)NTOK*DFF_];
__device__ __half g_gact[(size_t)NTOK*DFF_];
__device__ __half g_wqkv[(size_t)NLAYER*DD*3*DD];
__device__ __half g_wo[(size_t)NLAYER*DD*DD];
__device__ __half g_wg[(size_t)NLAYER*DD*DFF_];
__device__ __half g_wu[(size_t)NLAYER*DD*DFF_];
__device__ __half g_wd[(size_t)NLAYER*DFF_*DD];

// ---------------- PTX helpers ----------------
__device__ __forceinline__ uint32_t smem_u32(const void* p) {
    return (uint32_t)__cvta_generic_to_shared(p);
}
__device__ __forceinline__ void cp16(uint32_t s, const void* g) {
    asm volatile("cp.async.cg.shared.global [%0], [%1], 16;\n" :: "r"(s), "l"(g));
}
__device__ __forceinline__ void cp_commit() { asm volatile("cp.async.commit_group;\n"); }
__device__ __forceinline__ void cp_wait0()  { asm volatile("cp.async.wait_group 0;\n"); }
__device__ __forceinline__ void cp_wait1()  { asm volatile("cp.async.wait_group 1;\n"); }

__device__ __forceinline__ void ldmx4(uint32_t* r, uint32_t a) {
    asm volatile("ldmatrix.sync.aligned.m8n8.x4.shared.b16 {%0,%1,%2,%3}, [%4];\n"
        : "=r"(r[0]), "=r"(r[1]), "=r"(r[2]), "=r"(r[3]) : "r"(a));
}
__device__ __forceinline__ void ldmx4t(uint32_t* r, uint32_t a) {
    asm volatile("ldmatrix.sync.aligned.m8n8.x4.trans.shared.b16 {%0,%1,%2,%3}, [%4];\n"
        : "=r"(r[0]), "=r"(r[1]), "=r"(r[2]), "=r"(r[3]) : "r"(a));
}
__device__ __forceinline__ void mma_f16(float* c, const uint32_t* a, const uint32_t* b) {
    asm volatile("mma.sync.aligned.m16n8k16.row.col.f32.f16.f16.f32 "
        "{%0,%1,%2,%3}, {%4,%5,%6,%7}, {%8,%9}, {%0,%1,%2,%3};\n"
        : "+f"(c[0]), "+f"(c[1]), "+f"(c[2]), "+f"(c[3])
        : "r"(a[0]), "r"(a[1]), "r"(a[2]), "r"(a[3]), "r"(b[0]), "r"(b[1]));
}
__device__ __forceinline__ float ex2f(float x) {
    float y; asm("ex2.approx.ftz.f32 %0, %1;" : "=f"(y) : "f"(x)); return y;
}

// ---------------- float -> half cast ----------------
__global__ void cast_f2h(const float* __restrict__ s, __half* __restrict__ d, long n) {
    long i = ((long)blockIdx.x * blockDim.x + threadIdx.x) * 4;
    if (i < n) {
        float4 v = *(const float4*)(s + i);
        __half2* o = (__half2*)(d + i);
        o[0] = __floats2half2_rn(v.x, v.y);
        o[1] = __floats2half2_rn(v.z, v.w);
    }
}

// ---------------- rmsnorm ----------------
template<int OUTH>
__global__ void rmsnorm_kernel(const float* __restrict__ in, const float* __restrict__ w,
                               void* __restrict__ outv) {
    int row = blockIdx.x;
    int t = threadIdx.x;  // 256
    float4 v = ((const float4*)(in + (size_t)row * DD))[t];
    float ss = v.x*v.x + v.y*v.y + v.z*v.z + v.w*v.w;
    __shared__ float red[256];
    red[t] = ss;
    __syncthreads();
    for (int s = 128; s > 0; s >>= 1) {
        if (t < s) red[t] += red[t + s];
        __syncthreads();
    }
    float rinv = rsqrtf(red[0] * (1.0f / DD) + EPSV);
    float4 wv = ((const float4*)w)[t];
    float o0 = v.x * rinv * wv.x, o1 = v.y * rinv * wv.y;
    float o2 = v.z * rinv * wv.z, o3 = v.w * rinv * wv.w;
    if (OUTH) {
        __half2* o = (__half2*)((__half*)outv + (size_t)row * DD) + 2 * t;
        o[0] = __floats2half2_rn(o0, o1);
        o[1] = __floats2half2_rn(o2, o3);
    } else {
        float4 o; o.x = o0; o.y = o1; o.z = o2; o.w = o3;
        ((float4*)((float*)outv + (size_t)row * DD))[t] = o;
    }
}

// ---------------- mma GEMM: 256 threads, BM=128 BN=128 BK=32, 3-stage ----------------
// A [M,K] fp16 row-major, B [K,N] fp16 row-major. OUT: 1 = fp32 out + res, 2 = fp16 out.
template<int OUT>
__global__ void __launch_bounds__(256)
gemm_mma(const __half* __restrict__ A, const __half* __restrict__ B,
         const float* __restrict__ Res, void* __restrict__ Cv,
         int N, int K)
{
    constexpr int AP = 40;       // 32 + 8 pad
    constexpr int BP = 136;      // 128 + 8 pad
    constexpr int ASZ = 128 * AP;
    constexpr int BSZ = 32 * BP;
    extern __shared__ __half sm[];
    __half* As = sm;                    // 3 stages
    __half* Bs = sm + 3 * ASZ;

    const int tid = threadIdx.x, warp = tid >> 5, lane = tid & 31;
    const int wm = warp >> 2, wn = warp & 3;
    const long row0 = (long)blockIdx.y * 128;
    const long col0 = (long)blockIdx.x * 128;

    float acc[4][4][4];
#pragma unroll
    for (int i = 0; i < 4; i++)
#pragma unroll
        for (int j = 0; j < 4; j++)
#pragma unroll
            for (int q = 0; q < 4; q++) acc[i][j][q] = 0.f;

    const int TK = K >> 5;
    auto load = [&](int s, int kt) {
        const int kb = kt * 32;
#pragma unroll
        for (int i = 0; i < 2; i++) {
            int lin = tid + i * 256;
            int r = lin >> 2, c = (lin & 3) * 8;
            cp16(smem_u32(&As[s * ASZ + r * AP + c]), A + (row0 + r) * (size_t)K + kb + c);
        }
#pragma unroll
        for (int i = 0; i < 2; i++) {
            int lin = tid + i * 256;
            int r = lin >> 4, c = (lin & 15) * 8;
            cp16(smem_u32(&Bs[s * BSZ + r * BP + c]), B + (size_t)(kb + r) * N + col0 + c);
        }
    };

    load(0, 0); cp_commit();
    load(1, 1); cp_commit();
    for (int t = 0; t < TK; t++) {
        if (t == TK - 1) cp_wait0(); else cp_wait1();
        __syncthreads();
        if (t + 2 < TK) { load((t + 2) % 3, t + 2); cp_commit(); }
        const __half* as = &As[(t % 3) * ASZ];
        const __half* bs = &Bs[(t % 3) * BSZ];
#pragma unroll
        for (int ks = 0; ks < 2; ks++) {
            const int k0 = ks * 16;
            uint32_t a[4][4];
#pragma unroll
            for (int mt = 0; mt < 4; mt++) {
                int r = wm * 64 + mt * 16 + (lane & 15);
                int c = k0 + (lane >> 4) * 8;
                ldmx4(a[mt], smem_u32(&as[r * AP + c]));
            }
            uint32_t bf[4][2];
#pragma unroll
            for (int np = 0; np < 2; np++) {
                int r = k0 + (lane & 15);
                int c = wn * 32 + np * 16 + (lane >> 4) * 8;
                uint32_t rr[4];
                ldmx4t(rr, smem_u32(&bs[r * BP + c]));
                bf[np*2][0] = rr[0]; bf[np*2][1] = rr[1];
                bf[np*2+1][0] = rr[2]; bf[np*2+1][1] = rr[3];
            }
#pragma unroll
            for (int mt = 0; mt < 4; mt++)
#pragma unroll
                for (int nt = 0; nt < 4; nt++)
                    mma_f16(acc[mt][nt], a[mt], bf[nt]);
        }
        __syncthreads();
    }

#pragma unroll
    for (int mt = 0; mt < 4; mt++) {
        long r = row0 + wm * 64 + mt * 16 + (lane >> 2);
#pragma unroll
        for (int nt = 0; nt < 4; nt++) {
            long c = col0 + wn * 32 + nt * 8 + (lane & 3) * 2;
            float* ac = acc[mt][nt];
            if (OUT == 2) {
                __half* C = (__half*)Cv;
                *(__half2*)(C + r * N + c)       = __floats2half2_rn(ac[0], ac[1]);
                *(__half2*)(C + (r + 8) * N + c) = __floats2half2_rn(ac[2], ac[3]);
            } else {
                float* C = (float*)Cv;
                float2 r0 = *(const float2*)(Res + r * N + c);
                float2 r1 = *(const float2*)(Res + (r + 8) * N + c);
                *(float2*)(C + r * N + c)       = make_float2(ac[0] + r0.x, ac[1] + r0.y);
                *(float2*)(C + (r + 8) * N + c) = make_float2(ac[2] + r1.x, ac[3] + r1.y);
            }
        }
    }
}

// ---------------- per-head rmsnorm + RoPE + split (q pre-scaled) ----------------
__global__ void qk_prep_kernel(const __half* __restrict__ qkv, const float* __restrict__ qw,
                               const float* __restrict__ kw, const int* __restrict__ positions,
                               __half* __restrict__ qh, __half* __restrict__ kh,
                               __half* __restrict__ vh) {
    int bl = blockIdx.x;
    int b = bl >> 10, l = bl & 1023;
    int warp = threadIdx.x >> 5;
    int lane = threadIdx.x & 31;
    int isk = warp >> 4;
    int h = warp & 15;
    const __half* base = qkv + (size_t)bl * 3 * DD + isk * DD + h * DH;
    const float* w = isk ? kw : qw;
    float2 v = __half22float2(*(const __half2*)(base + 2 * lane));
    float ss = v.x * v.x + v.y * v.y;
#pragma unroll
    for (int o = 16; o > 0; o >>= 1) ss += __shfl_xor_sync(0xffffffffu, ss, o);
    float rinv = rsqrtf(ss * (1.0f / DH) + EPSV);
    float n0 = v.x * rinv * w[2 * lane];
    float n1 = v.y * rinv * w[2 * lane + 1];
    float o0 = n0, o1 = n1;
    if (lane < 16) {
        float pos = (float)positions[bl];
        float th = pos * expf(-0.5756462732485115f * (float)lane);
        float c = cosf(th), s = sinf(th);
        o0 = n0 * c - n1 * s;
        o1 = n0 * s + n1 * c;
    }
    if (!isk) { o0 *= QSCALE; o1 *= QSCALE; }   // fold softmax scale * log2(e) into q
    __half* outp = (isk ? kh : qh) + (((size_t)(b * HH + h)) * LL + l) * DH + 2 * lane;
    *(__half2*)outp = __floats2half2_rn(o0, o1);
    if (!isk) {
        __half2 vv = *(const __half2*)(qkv + (size_t)bl * 3 * DD + 2 * DD + h * DH + 2 * lane);
        *(__half2*)(vh + (((size_t)(b * HH + h)) * LL + l) * DH + 2 * lane) = vv;
    }
}

// ---------------- flash attention ----------------
// grid (L/128, B*H); 128 threads (4 warps, 32 q-rows each). KV tiles of 64, double buffered.
// Q pre-scaled by 1/sqrt(Dh)*log2e; bias multiplied by log2e here; softmax in exp2 domain.
__global__ void __launch_bounds__(128)
flash_attn(const __half* __restrict__ Q, const __half* __restrict__ Kh,
           const __half* __restrict__ V, const int* __restrict__ var_id,
           const float* __restrict__ bias_l, __half* __restrict__ O)
{
    constexpr int P72 = DH + 8;
    constexpr int KSZ = 64 * P72;     // halves per stage
    extern __shared__ __half sm[];
    __half* Qs = sm;                  // 128*72
    __half* Ks = sm + 128 * P72;      // 2 stages
    __half* Vs = Ks + 2 * KSZ;        // 2 stages
    int*    vks = (int*)(Vs + 2 * KSZ);  // 2 stages x 64

    const int zbh = blockIdx.y;
    const int b = zbh >> 4, h = zbh & 15;
    const int q0 = blockIdx.x * 128;
    const int tid = threadIdx.x, warp = tid >> 5, lane = tid & 31;
    const int g = lane >> 2;           // group row
    const int wq = warp * 32;

    const __half* Qz = Q + ((size_t)zbh * LL + q0) * DH;
    const __half* Kz = Kh + (size_t)zbh * LL * DH;
    const __half* Vz = V + (size_t)zbh * LL * DH;

    // Q tile -> smem (group 0 includes KV tile 0)
#pragma unroll
    for (int i = 0; i < 8; i++) {
        int lin = tid + i * 128;
        int r = lin >> 3, c = (lin & 7) * 8;
        cp16(smem_u32(&Qs[r * P72 + c]), Qz + (size_t)r * DH + c);
    }
    auto load_tile = [&](int s, int kt) {
        int kb = kt * 64;
#pragma unroll
        for (int i = 0; i < 4; i++) {
            int lin = tid + i * 128;
            int r = lin >> 3, c = (lin & 7) * 8;
            cp16(smem_u32(&Ks[s * KSZ + r * P72 + c]), Kz + (size_t)(kb + r) * DH + c);
            cp16(smem_u32(&Vs[s * KSZ + r * P72 + c]), Vz + (size_t)(kb + r) * DH + c);
        }
        if (tid < 16)
            cp16(smem_u32(&vks[s * 64 + tid * 4]), var_id + b * LL + kb + tid * 4);
    };
    load_tile(0, 0);
    cp_commit();

    // per-thread q var-ids (rows g, g+8 of each mtile)
    int vq[2][2];
#pragma unroll
    for (int mt = 0; mt < 2; mt++) {
        vq[mt][0] = var_id[b * LL + q0 + wq + mt * 16 + g];
        vq[mt][1] = var_id[b * LL + q0 + wq + mt * 16 + g + 8];
    }
    const float bd = bias_l[h] * LOG2E;
    const float bs = bias_l[HH + h] * LOG2E;

    uint32_t qf[2][4][4];                 // [mtile][kstep][4]
    float oacc[2][8][4];
    float m[2][2], lsum[2][2];
#pragma unroll
    for (int mt = 0; mt < 2; mt++)
#pragma unroll
        for (int nt = 0; nt < 8; nt++)
#pragma unroll
            for (int q = 0; q < 4; q++) oacc[mt][nt][q] = 0.f;
#pragma unroll
    for (int mt = 0; mt < 2; mt++)
        for (int ri = 0; ri < 2; ri++) { m[mt][ri] = -1e30f; lsum[mt][ri] = 0.f; }

    for (int it = 0; it < LL / 64; it++) {
        if (it + 1 < LL / 64) { load_tile((it + 1) & 1, it + 1); cp_commit(); cp_wait1(); }
        else cp_wait0();
        __syncthreads();
        const int s = it & 1;
        if (it == 0) {
#pragma unroll
            for (int mt = 0; mt < 2; mt++)
#pragma unroll
                for (int ks = 0; ks < 4; ks++) {
                    int r = wq + mt * 16 + (lane & 15);
                    int c = ks * 16 + (lane >> 4) * 8;
                    ldmx4(qf[mt][ks], smem_u32(&Qs[r * P72 + c]));
                }
        }

        // ---- S = Q K^T ----
        float sacc[2][8][4];
#pragma unroll
        for (int mt = 0; mt < 2; mt++)
#pragma unroll
            for (int nt = 0; nt < 8; nt++)
#pragma unroll
                for (int q = 0; q < 4; q++) sacc[mt][nt][q] = 0.f;
#pragma unroll
        for (int ks = 0; ks < 4; ks++) {
            int k0 = ks * 16;
            uint32_t bf[8][2];
#pragma unroll
            for (int np = 0; np < 4; np++) {
                int r = np * 16 + (lane & 7) + ((lane >> 4) & 1) * 8;
                int c = k0 + ((lane >> 3) & 1) * 8;
                uint32_t rr[4];
                ldmx4(rr, smem_u32(&Ks[s * KSZ + r * P72 + c]));
                bf[np*2][0] = rr[0]; bf[np*2][1] = rr[1];
                bf[np*2+1][0] = rr[2]; bf[np*2+1][1] = rr[3];
            }
#pragma unroll
            for (int mt = 0; mt < 2; mt++)
#pragma unroll
                for (int nt = 0; nt < 8; nt++)
                    mma_f16(sacc[mt][nt], qf[mt][ks], bf[nt]);
        }

        // ---- bias + online softmax ----
        uint32_t pf[2][8][2];   // P as half2 pairs: [mt][nt][{rows g, g+8}]
#pragma unroll
        for (int mt = 0; mt < 2; mt++) {
            float tm0 = -1e30f, tm1 = -1e30f;
#pragma unroll
            for (int nt = 0; nt < 8; nt++) {
                int cl = nt * 8 + (lane & 3) * 2;
                int w0 = vks[s * 64 + cl], w1 = vks[s * 64 + cl + 1];
                float* ac = sacc[mt][nt];
                ac[0] += (vq[mt][0] == w0) ? bs : bd;
                ac[1] += (vq[mt][0] == w1) ? bs : bd;
                ac[2] += (vq[mt][1] == w0) ? bs : bd;
                ac[3] += (vq[mt][1] == w1) ? bs : bd;
                tm0 = fmaxf(tm0, fmaxf(ac[0], ac[1]));
                tm1 = fmaxf(tm1, fmaxf(ac[2], ac[3]));
            }
            tm0 = fmaxf(tm0, __shfl_xor_sync(0xffffffffu, tm0, 1));
            tm0 = fmaxf(tm0, __shfl_xor_sync(0xffffffffu, tm0, 2));
            tm1 = fmaxf(tm1, __shfl_xor_sync(0xffffffffu, tm1, 1));
            tm1 = fmaxf(tm1, __shfl_xor_sync(0xffffffffu, tm1, 2));
            float mn0 = fmaxf(m[mt][0], tm0), mn1 = fmaxf(m[mt][1], tm1);
            float cr0 = ex2f(m[mt][0] - mn0), cr1 = ex2f(m[mt][1] - mn1);
            m[mt][0] = mn0; m[mt][1] = mn1;
            float rs0 = 0.f, rs1 = 0.f;
#pragma unroll
            for (int nt = 0; nt < 8; nt++) {
                float* ac = sacc[mt][nt];
                float p0 = ex2f(ac[0] - mn0), p1 = ex2f(ac[1] - mn0);
                float p2 = ex2f(ac[2] - mn1), p3 = ex2f(ac[3] - mn1);
                rs0 += p0 + p1; rs1 += p2 + p3;
                __half2 h0 = __floats2half2_rn(p0, p1);
                __half2 h1 = __floats2half2_rn(p2, p3);
                pf[mt][nt][0] = *(uint32_t*)&h0;
                pf[mt][nt][1] = *(uint32_t*)&h1;
                float* oc = oacc[mt][nt];
                oc[0] *= cr0; oc[1] *= cr0; oc[2] *= cr1; oc[3] *= cr1;
            }
            rs0 += __shfl_xor_sync(0xffffffffu, rs0, 1);
            rs0 += __shfl_xor_sync(0xffffffffu, rs0, 2);
            rs1 += __shfl_xor_sync(0xffffffffu, rs1, 1);
            rs1 += __shfl_xor_sync(0xffffffffu, rs1, 2);
            lsum[mt][0] = lsum[mt][0] * cr0 + rs0;
            lsum[mt][1] = lsum[mt][1] * cr1 + rs1;
        }

        // ---- O += P V ----
#pragma unroll
        for (int ks = 0; ks < 4; ks++) {
            uint32_t bf[8][2];
#pragma unroll
            for (int np = 0; np < 4; np++) {
                int r = ks * 16 + (lane & 15);
                int c = np * 16 + (lane >> 4) * 8;
                uint32_t rr[4];
                ldmx4t(rr, smem_u32(&Vs[s * KSZ + r * P72 + c]));
                bf[np*2][0] = rr[0]; bf[np*2][1] = rr[1];
                bf[np*2+1][0] = rr[2]; bf[np*2+1][1] = rr[3];
            }
#pragma unroll
            for (int mt = 0; mt < 2; mt++) {
                uint32_t a[4];
                a[0] = pf[mt][2*ks][0];   a[1] = pf[mt][2*ks][1];
                a[2] = pf[mt][2*ks+1][0]; a[3] = pf[mt][2*ks+1][1];
#pragma unroll
                for (int nt = 0; nt < 8; nt++)
                    mma_f16(oacc[mt][nt], a, bf[nt]);
            }
        }
        __syncthreads();
    }

    // ---- finalize: O /= l, write [tok][h*64+d] ----
#pragma unroll
    for (int mt = 0; mt < 2; mt++) {
        float inv0 = 1.0f / lsum[mt][0], inv1 = 1.0f / lsum[mt][1];
        int r = q0 + wq + mt * 16 + g;
#pragma unroll
        for (int nt = 0; nt < 8; nt++) {
            int c = h * DH + nt * 8 + (lane & 3) * 2;
            float* oc = oacc[mt][nt];
            *(__half2*)(O + ((size_t)(b * LL + r)) * DD + c) =
                __floats2half2_rn(oc[0] * inv0, oc[1] * inv0);
            *(__half2*)(O + ((size_t)(b * LL + r + 8)) * DD + c) =
                __floats2half2_rn(oc[2] * inv1, oc[3] * inv1);
        }
    }
}

// ---------------- silu(gate) * up -> fp16 ----------------
__global__ void silu_mul_kernel(const __half* __restrict__ g, const __half* __restrict__ u,
                                __half* __restrict__ o) {
    size_t i = (size_t)blockIdx.x * blockDim.x + threadIdx.x;
    float2 gf = __half22float2(((const __half2*)g)[i]);
    float2 uf = __half22float2(((const __half2*)u)[i]);
    float r0 = (gf.x / (1.f + expf(-gf.x))) * uf.x;
    float r1 = (gf.y / (1.f + expf(-gf.y))) * uf.y;
    ((__half2*)o)[i] = __floats2half2_rn(r0, r1);
}

// ---------------- host orchestration ----------------
extern "C" void kernel_launch(void* const* d_in, const int* in_sizes, int n_in,
                              void* d_out, int out_size) {
    const float* x         = (const float*)d_in[0];
    const int*   var_id    = (const int*)d_in[1];
    const int*   positions = (const int*)d_in[2];
    const float* Wqkv      = (const float*)d_in[3];
    const float* Wo        = (const float*)d_in[4];
    const float* n1w       = (const float*)d_in[5];
    const float* n2w       = (const float*)d_in[6];
    const float* qnw       = (const float*)d_in[7];
    const float* knw       = (const float*)d_in[8];
    const float* bias_emb  = (const float*)d_in[9];
    const float* Wg        = (const float*)d_in[10];
    const float* Wu        = (const float*)d_in[11];
    const float* Wd        = (const float*)d_in[12];
    const float* fnw       = (const float*)d_in[13];
    float* out = (float*)d_out;

    float  *h;
    __half *yh, *qkv, *qh, *kh, *vh, *attno, *gate, *up, *gact;
    __half *wqkv, *wo, *wg, *wu, *wd;
    cudaGetSymbolAddress((void**)&h, g_h);
    cudaGetSymbolAddress((void**)&yh, g_yh);
    cudaGetSymbolAddress((void**)&qkv, g_qkv);
    cudaGetSymbolAddress((void**)&qh, g_qh);
    cudaGetSymbolAddress((void**)&kh, g_kh);
    cudaGetSymbolAddress((void**)&vh, g_vh);
    cudaGetSymbolAddress((void**)&attno, g_attno);
    cudaGetSymbolAddress((void**)&gate, g_gate);
    cudaGetSymbolAddress((void**)&up, g_up);
    cudaGetSymbolAddress((void**)&gact, g_gact);
    cudaGetSymbolAddress((void**)&wqkv, g_wqkv);
    cudaGetSymbolAddress((void**)&wo, g_wo);
    cudaGetSymbolAddress((void**)&wg, g_wg);
    cudaGetSymbolAddress((void**)&wu, g_wu);
    cudaGetSymbolAddress((void**)&wd, g_wd);

    const int GEMM_SMEM = 3 * (128*40 + 32*136) * 2;        // 56832
    const int FLASH_SMEM = (128*72 + 2*64*72 + 2*64*72) * 2 + 2*64*4;  // 55808
    cudaFuncSetAttribute(gemm_mma<1>, cudaFuncAttributeMaxDynamicSharedMemorySize, GEMM_SMEM);
    cudaFuncSetAttribute(gemm_mma<2>, cudaFuncAttributeMaxDynamicSharedMemorySize, GEMM_SMEM);
    cudaFuncSetAttribute(flash_attn, cudaFuncAttributeMaxDynamicSharedMemorySize, FLASH_SMEM);

    auto cast = [](const float* s, __half* d, long n) {
        cast_f2h<<<(unsigned)((n / 4 + 255) / 256), 256>>>(s, d, n);
    };
    cast(Wqkv, wqkv, (long)NLAYER * DD * 3 * DD);
    cast(Wo,   wo,   (long)NLAYER * DD * DD);
    cast(Wg,   wg,   (long)NLAYER * DD * DFF_);
    cast(Wu,   wu,   (long)NLAYER * DD * DFF_);
    cast(Wd,   wd,   (long)NLAYER * DFF_ * DD);

    cudaMemcpyAsync(h, x, (size_t)NTOK * DD * sizeof(float), cudaMemcpyDeviceToDevice);

    for (int l = 0; l < NLAYER; l++) {
        // ---- attention ----
        rmsnorm_kernel<1><<<NTOK, 256>>>(h, n1w + (size_t)l * DD, yh);
        gemm_mma<2><<<dim3(3 * DD / 128, NTOK / 128), 256, GEMM_SMEM>>>(
            yh, wqkv + (size_t)l * DD * 3 * DD, nullptr, qkv, 3 * DD, DD);
        qk_prep_kernel<<<NTOK, 1024>>>(qkv, qnw + (size_t)l * DH, knw + (size_t)l * DH,
                                       positions, qh, kh, vh);
        flash_attn<<<dim3(LL / 128, BB * HH), 128, FLASH_SMEM>>>(
            qh, kh, vh, var_id, bias_emb + (size_t)l * 2 * HH, attno);
        gemm_mma<1><<<dim3(DD / 128, NTOK / 128), 256, GEMM_SMEM>>>(
            attno, wo + (size_t)l * DD * DD, h, h, DD, DD);

        // ---- FFN ----
        rmsnorm_kernel<1><<<NTOK, 256>>>(h, n2w + (size_t)l * DD, yh);
        gemm_mma<2><<<dim3(DFF_ / 128, NTOK / 128), 256, GEMM_SMEM>>>(
            yh, wg + (size_t)l * DD * DFF_, nullptr, gate, DFF_, DD);
        gemm_mma<2><<<dim3(DFF_ / 128, NTOK / 128), 256, GEMM_SMEM>>>(
            yh, wu + (size_t)l * DD * DFF_, nullptr, up, DFF_, DD);
        silu_mul_kernel<<<(unsigned)(((size_t)NTOK * DFF_ / 2) / 256), 256>>>(gate, up, gact);
        gemm_mma<1><<<dim3(DD / 128, NTOK / 128), 256, GEMM_SMEM>>>(
            gact, wd + (size_t)l * DFF_ * DD, h, h, DD, DFF_);
    }

    rmsnorm_kernel<0><<<NTOK, 256>>>(h, fnw, out);
}